// round 4
// baseline (speedup 1.0000x reference)
#include <cuda_runtime.h>
#include <stdint.h>

#define THREADS   256
#define GRID      2368
#define WARPS_PB  (THREADS / 32)
#define WBUF      512u                       /* per-warp staging entries */
#define CAND_CAP  (16u * 1024u * 1024u)      /* 64 MB candidate buffer */
#define CUTBITS   0x40000000u                /* bit pattern of 2.0f */

__device__ unsigned           g_hist20[1u << 20]; // hist over u>>11, candidates only
__device__ unsigned           g_part[1024];       // per-chunk partial sums
__device__ unsigned           g_fine[2048];       // low-11-bit fine hist
__device__ unsigned           g_fb[1u << 20];     // fallback-only scratch
__device__ unsigned           g_cand[CAND_CAP];   // compacted candidate patterns
__device__ unsigned           g_cur;              // global candidate cursor
__device__ unsigned long long g_zeros;
__device__ int                g_need;             // th < 2.0 -> full fallback
__device__ int                g_ovf;              // candidate buffer overflow
__device__ long long          g_idx;
__device__ int                g_bin;              // 20-bit target bin B (u>>11)
__device__ long long          g_rank;             // rank within B
__device__ float              g_th;
__device__ float              g_step;

// ---------------- shuffle-based inclusive scan over 1024 threads (race-safe reuse)
__device__ unsigned block_scan_1024(unsigned v, int t, unsigned* total) {
    __shared__ unsigned wt[32];
    unsigned s = v;
    for (int o = 1; o < 32; o <<= 1) {
        unsigned u = __shfl_up_sync(0xffffffffu, s, o);
        if ((t & 31) >= o) s += u;
    }
    if ((t & 31) == 31) wt[t >> 5] = s;
    __syncthreads();
    if (t < 32) {
        unsigned w = wt[t];
        for (int o = 1; o < 32; o <<= 1) {
            unsigned u = __shfl_up_sync(0xffffffffu, w, o);
            if (t >= o) w += u;
        }
        wt[t] = w;
    }
    __syncthreads();
    if (t >= 32) s += wt[(t >> 5) - 1];
    *total = wt[31];
    __syncthreads();   // protect wt against immediate reuse
    return s;
}

// ---------------- Pass 1: candidate compaction + 20-bit hist (RED) + zero count
__device__ __forceinline__ void warp_flush(unsigned* __restrict__ buf,
                                           unsigned* scnt_w, int lane) {
    unsigned c = *scnt_w;
    unsigned base = 0u;
    if (lane == 0) base = atomicAdd(&g_cur, c);
    base = __shfl_sync(0xffffffffu, base, 0);
    if (base + c <= CAND_CAP) {
        for (unsigned j = lane; j < c; j += 32u) g_cand[base + j] = buf[j];
    } else if (lane == 0) {
        g_ovf = 1;
    }
    __syncwarp();
    if (lane == 0) *scnt_w = 0u;
    __syncwarp();
}

__global__ void __launch_bounds__(THREADS) pass1(const uint4* __restrict__ x4,
                                                 int n4, int n) {
    __shared__ unsigned sbuf[WARPS_PB][WBUF];
    __shared__ unsigned scnt[WARPS_PB];
    int tid = threadIdx.x, lane = tid & 31, warp = tid >> 5;
    if (lane == 0) scnt[warp] = 0u;
    __syncwarp();
    unsigned* buf = sbuf[warp];
    unsigned* cnt = &scnt[warp];
    unsigned zeros = 0u;

#define P1_PROC(r) do { \
        unsigned u = (r) & 0x7fffffffu; \
        if (act && u >= CUTBITS) { \
            atomicAdd(&g_hist20[u >> 11], 1u);      /* RED, no return */ \
            unsigned p = atomicAdd(cnt, 1u); \
            buf[p] = u; \
        } else if (act) { \
            zeros += (u == 0u) ? 1u : 0u; \
        } \
    } while (0)

    for (int base = blockIdx.x * THREADS + warp * 32; base < n4; base += GRID * THREADS) {
        __syncwarp();
        if (*cnt >= WBUF - 128u) warp_flush(buf, cnt, lane);   // warp-uniform
        int i = base + lane;
        bool act = (i < n4);
        uint4 v = act ? x4[i] : make_uint4(0u, 0u, 0u, 0u);
        P1_PROC(v.x); P1_PROC(v.y); P1_PROC(v.z); P1_PROC(v.w);
    }
    // tail (n % 4): block 0, warp 0
    if (blockIdx.x == 0 && warp == 0) {
        __syncwarp();
        if (*cnt >= WBUF - 32u) warp_flush(buf, cnt, lane);
        int i = (n4 << 2) + lane;
        bool act = (i < n);
        unsigned r = act ? ((const unsigned*)x4)[i] : 0u;
        P1_PROC(r);
    }
#undef P1_PROC
    __syncwarp();
    warp_flush(buf, cnt, lane);   // final drain

    for (int o = 16; o; o >>= 1) zeros += __shfl_down_sync(0xffffffffu, zeros, o);
    if (lane == 0 && zeros) atomicAdd(&g_zeros, (unsigned long long)zeros);
}

// ---------------- Scan A: per-chunk partial sums of 20-bit hist
__global__ void __launch_bounds__(THREADS) scan2a() {
    __shared__ unsigned red[THREADS / 32];
    int b = blockIdx.x;
    int tid = threadIdx.x;
    unsigned sum = 0u;
    for (int i = tid; i < 1024; i += THREADS) sum += g_hist20[b * 1024 + i];
    for (int o = 16; o; o >>= 1) sum += __shfl_down_sync(0xffffffffu, sum, o);
    if ((tid & 31) == 0) red[tid >> 5] = sum;
    __syncthreads();
    if (tid == 0) {
        unsigned tot = 0u;
        for (int w = 0; w < THREADS / 32; w++) tot += red[w];
        g_part[b] = tot;
    }
}

// ---------------- Scan B: idx computation + locate 20-bit bin B + rank
__global__ void scan2b(long long n) {
    __shared__ int sc;
    __shared__ long long sr;
    int t = threadIdx.x;
    unsigned tot;
    unsigned c = g_part[t];
    unsigned incl = block_scan_1024(c, t, &tot);

    long long zeros = (long long)g_zeros;
    long long below = n - (long long)tot;      // elements with |x| < 2.0
    long long nnz = n - zeros;
    long long idx = (long long)floorf(0.997f * (float)nnz) + (n - nnz);
    if (idx > n - 1) idx = n - 1;
    if (idx < 0) idx = 0;
    int need = (below > idx) ? 1 : 0;
    if (t == 0) { g_need = need; g_idx = idx; }
    if (need) return;

    long long r = idx - below;
    long long inclL = (long long)incl;
    long long exclL = inclL - (long long)c;
    if (r >= exclL && r < inclL) { sc = t; sr = r - exclL; }
    __syncthreads();
    int chunk = sc;
    long long r2 = sr;
    unsigned c2 = g_hist20[(unsigned)chunk * 1024u + (unsigned)t];
    unsigned incl2 = block_scan_1024(c2, t, &tot);
    long long incl2L = (long long)incl2;
    long long excl2L = incl2L - (long long)c2;
    if (r2 >= excl2L && r2 < incl2L) {
        g_bin = chunk * 1024 + t;
        g_rank = r2 - excl2L;
    }
}

// ---------------- Fallback (single block, exact, only if th < 2.0): full 31-bit selection
__global__ void fbk(const uint4* __restrict__ x4, int n4, int n) {
    if (!g_need) return;
    __shared__ unsigned sh[2048];
    __shared__ int sbin, sch;
    __shared__ long long srank, sr3;
    int t = threadIdx.x;                 // 1024 threads
    sh[t] = 0u; sh[t + 1024] = 0u;
    __syncthreads();
    int rem = n - (n4 << 2);
    for (int i = t; i < n4; i += 1024) {
        uint4 v = x4[i];
        atomicAdd(&sh[(v.x & 0x7fffffffu) >> 20], 1u);
        atomicAdd(&sh[(v.y & 0x7fffffffu) >> 20], 1u);
        atomicAdd(&sh[(v.z & 0x7fffffffu) >> 20], 1u);
        atomicAdd(&sh[(v.w & 0x7fffffffu) >> 20], 1u);
    }
    if (t < rem) atomicAdd(&sh[(((const unsigned*)x4)[(n4 << 2) + t] & 0x7fffffffu) >> 20], 1u);
    __syncthreads();
    unsigned tot;
    unsigned c0 = sh[2 * t], c1 = sh[2 * t + 1];
    unsigned incl = block_scan_1024(c0 + c1, t, &tot);
    long long r = g_idx;
    long long inclL = (long long)incl, exclL = inclL - (long long)(c0 + c1);
    if (r >= exclL && r < inclL) {
        if (r < exclL + (long long)c0) { sbin = 2 * t;     srank = r - exclL; }
        else                           { sbin = 2 * t + 1; srank = r - exclL - (long long)c0; }
    }
    __syncthreads();
    unsigned cb = (unsigned)sbin;
    long long r2 = srank;
    for (unsigned i = t; i < (1u << 20); i += 1024u) g_fb[i] = 0u;
    __syncthreads();
    for (int i = t; i < n4; i += 1024) {
        uint4 v = x4[i];
#define FB(r_) do { unsigned u = (r_) & 0x7fffffffu; \
        if ((u >> 20) == cb) atomicAdd(&g_fb[u & 0xFFFFFu], 1u); } while (0)
        FB(v.x); FB(v.y); FB(v.z); FB(v.w);
    }
    if (t < rem) { FB(((const unsigned*)x4)[(n4 << 2) + t]); }
#undef FB
    __syncthreads();
    unsigned s = 0u;
    for (int j = 0; j < 1024; j++) s += g_fb[t * 1024 + j];
    unsigned incl3 = block_scan_1024(s, t, &tot);
    long long incl3L = (long long)incl3, excl3L = incl3L - (long long)s;
    if (r2 >= excl3L && r2 < incl3L) { sch = t; sr3 = r2 - excl3L; }
    __syncthreads();
    int ch = sch;
    long long r3 = sr3;
    unsigned c4 = g_fb[(unsigned)ch * 1024u + (unsigned)t];
    unsigned incl4 = block_scan_1024(c4, t, &tot);
    long long incl4L = (long long)incl4, excl4L = incl4L - (long long)c4;
    if (r3 >= excl4L && r3 < incl4L) {
        unsigned bits = (cb << 20) | ((unsigned)ch * 1024u + (unsigned)t);
        float th = __uint_as_float(bits);
        g_th = th;
        g_step = th / 7.0f;
    }
}

// ---------------- Pass 2: fine hist (low 11 bits of bin B); ovf -> exact full re-read
__global__ void __launch_bounds__(THREADS) pass2c(const uint4* __restrict__ x4,
                                                  int n4, int n) {
    if (g_need) return;
    unsigned B = (unsigned)g_bin;
    unsigned stride = gridDim.x * blockDim.x;
    unsigned tid0 = blockIdx.x * blockDim.x + threadIdx.x;
    if (!g_ovf) {
        unsigned tot = g_cur;
        for (unsigned i = tid0; i < tot; i += stride) {
            unsigned u = g_cand[i];
            if ((u >> 11) == B) atomicAdd(&g_fine[u & 0x7FFu], 1u);
        }
    } else {
        for (int i = (int)tid0; i < n4; i += (int)stride) {
            uint4 v = x4[i];
#define P2(r_) do { unsigned u = (r_) & 0x7fffffffu; \
        if ((u >> 11) == B) atomicAdd(&g_fine[u & 0x7FFu], 1u); } while (0)
            P2(v.x); P2(v.y); P2(v.z); P2(v.w);
        }
        int rem = n - (n4 << 2);
        if ((int)tid0 < rem) { P2(((const unsigned*)x4)[(n4 << 2) + (int)tid0]); }
#undef P2
    }
}

// ---------------- Scan F: low-11-bit bin -> th, step
__global__ void scanF() {
    if (g_need) return;
    int t = threadIdx.x;
    unsigned tot;
    unsigned c0 = g_fine[2 * t], c1 = g_fine[2 * t + 1];
    unsigned incl = block_scan_1024(c0 + c1, t, &tot);
    long long r = g_rank;
    long long inclL = (long long)incl, exclL = inclL - (long long)(c0 + c1);
    if (r >= exclL && r < inclL) {
        unsigned j = (r < exclL + (long long)c0) ? (2u * (unsigned)t) : (2u * (unsigned)t + 1u);
        unsigned bits = ((unsigned)g_bin << 11) | j;
        float th = __uint_as_float(bits);
        g_th = th;
        g_step = th / 7.0f;   // n_lv_pos = 2^(4-1)-1 = 7
    }
}

// ---------------- Pass 3: quantize + state reset for next graph replay
__device__ __forceinline__ float quant1(float v, float th, float step) {
    if (fabsf(v) <= th) return rintf(v / step) * step;  // IEEE div + RN-even (matches XLA)
    return v;
}

__global__ void __launch_bounds__(THREADS) pass3(const float4* __restrict__ x4,
                                                 float4* __restrict__ o4,
                                                 int n4, int n) {
    int tid = threadIdx.x;
    float th = g_th;
    float step = g_step;
    bool doq = (th > 0.0f);
    int stride = gridDim.x * blockDim.x;
    for (int i = blockIdx.x * blockDim.x + tid; i < n4; i += stride) {
        float4 v = x4[i];
        if (doq) {
            v.x = quant1(v.x, th, step);
            v.y = quant1(v.y, th, step);
            v.z = quant1(v.z, th, step);
            v.w = quant1(v.w, th, step);
        }
        o4[i] = v;
    }
    int rem = n - (n4 << 2);
    if (blockIdx.x == 0 && tid < rem) {
        int i = (n4 << 2) + tid;
        float f = ((const float*)x4)[i];
        ((float*)o4)[i] = doq ? quant1(f, th, step) : f;
    }
    // ---- reset device state for the next replay (stream order makes this safe)
    unsigned t = blockIdx.x * blockDim.x + tid;
    unsigned T = gridDim.x * blockDim.x;
    for (unsigned i = t; i < (1u << 20); i += T) g_hist20[i] = 0u;
    if (t < 2048u) g_fine[t] = 0u;
    if (t == 0) { g_zeros = 0ull; g_cur = 0u; g_need = 0; g_ovf = 0; }
}

extern "C" void kernel_launch(void* const* d_in, const int* in_sizes, int n_in,
                              void* d_out, int out_size) {
    const float* x = (const float*)d_in[0];
    int n = in_sizes[0];
    int n4 = n >> 2;

    pass1<<<GRID, THREADS>>>((const uint4*)x, n4, n);
    scan2a<<<1024, THREADS>>>();
    scan2b<<<1, 1024>>>((long long)n);
    fbk<<<1, 1024>>>((const uint4*)x, n4, n);            // gated (g_need)
    pass2c<<<592, THREADS>>>((const uint4*)x, n4, n);    // fast: ~12 MB; ovf: exact full read
    scanF<<<1, 1024>>>();
    pass3<<<GRID, THREADS>>>((const float4*)x, (float4*)d_out, n4, n);
}

// round 5
// speedup vs baseline: 2.1975x; 2.1975x over previous
#include <cuda_runtime.h>
#include <stdint.h>

#define THREADS   256
#define GRID      2368
#define WARPS_PB  (THREADS / 32)
#define WBUF      256u                       /* per-warp staging entries */
#define CAND_CAP  (16u * 1024u * 1024u)      /* 64 MB candidate buffer */
#define CUTBITS   0x40000000u                /* bit pattern of 2.0f */

__device__ unsigned           g_hist1[1024];      // coarse bins u>>20 in [1024,2048)
__device__ unsigned           g_mid[2048];        // bits [19:9] within coarse bin
__device__ unsigned           g_low[512];         // bits [8:0] within mid bin
__device__ unsigned           g_fb[1u << 20];     // fallback-only scratch (self-zeroed)
__device__ unsigned           g_cand[CAND_CAP];   // compacted candidate patterns
__device__ unsigned           g_cur;              // global candidate cursor
__device__ unsigned long long g_zeros;
__device__ int                g_need;             // th < 2.0 -> full fallback
__device__ int                g_ovf;              // candidate buffer overflow
__device__ long long          g_idx;
__device__ int                g_bin20;            // target coarse bin (actual u>>20)
__device__ long long          g_rank;             // rank within coarse bin
__device__ unsigned           g_top21;            // bits [30:9] of target
__device__ long long          g_rank2;            // rank within mid bin
__device__ float              g_th;
__device__ float              g_step;

// ---------------- shuffle-based inclusive scan over 1024 threads (race-safe reuse)
__device__ unsigned block_scan_1024(unsigned v, int t, unsigned* total) {
    __shared__ unsigned wt[32];
    unsigned s = v;
    for (int o = 1; o < 32; o <<= 1) {
        unsigned u = __shfl_up_sync(0xffffffffu, s, o);
        if ((t & 31) >= o) s += u;
    }
    if ((t & 31) == 31) wt[t >> 5] = s;
    __syncthreads();
    if (t < 32) {
        unsigned w = wt[t];
        for (int o = 1; o < 32; o <<= 1) {
            unsigned u = __shfl_up_sync(0xffffffffu, w, o);
            if (t >= o) w += u;
        }
        wt[t] = w;
    }
    __syncthreads();
    if (t >= 32) s += wt[(t >> 5) - 1];
    *total = wt[31];
    __syncthreads();
    return s;
}

// ---------------- Pass 1: coarse hist (shared) + compaction + zeros (all on rare path)
__device__ __forceinline__ void warp_flush(unsigned* __restrict__ buf,
                                           unsigned* scnt_w, int lane) {
    unsigned c = *scnt_w;
    unsigned base = 0u;
    if (lane == 0) base = atomicAdd(&g_cur, c);
    base = __shfl_sync(0xffffffffu, base, 0);
    if (base + c <= CAND_CAP) {
        for (unsigned j = lane; j < c; j += 32u) g_cand[base + j] = buf[j];
    } else if (lane == 0) {
        g_ovf = 1;
    }
    __syncwarp();
    if (lane == 0) *scnt_w = 0u;
    __syncwarp();
}

__global__ void __launch_bounds__(THREADS, 8) pass1(const uint4* __restrict__ x4,
                                                    int n4a, int n) {
    __shared__ unsigned shist[1024];
    __shared__ unsigned sbuf[WARPS_PB][WBUF];
    __shared__ unsigned scnt[WARPS_PB];
    int tid = threadIdx.x, lane = tid & 31, warp = tid >> 5;
    for (int i = tid; i < 1024; i += THREADS) shist[i] = 0u;
    if (tid < WARPS_PB) scnt[tid] = 0u;
    __syncthreads();
    unsigned* buf = sbuf[warp];
    unsigned* cnt = &scnt[warp];
    unsigned zc = 0u;

#define P1_PROC(r) do { \
        unsigned u = (r) & 0x7fffffffu; \
        if ((u - 1u) >= (CUTBITS - 1u)) {        /* rare: candidate or zero */ \
            if (u == 0u) { zc += 1u; } \
            else { \
                atomicAdd(&shist[(u >> 20) - 1024u], 1u); \
                unsigned p = atomicAdd(cnt, 1u); \
                buf[p] = u; \
            } \
        } \
    } while (0)

    for (int base = blockIdx.x * THREADS + warp * 32; base < n4a; base += GRID * THREADS) {
        __syncwarp();
        if (*cnt >= WBUF - 128u) warp_flush(buf, cnt, lane);   // warp-uniform
        uint4 v = __ldcs(&x4[base + lane]);                    // n4a % 32 == 0
        P1_PROC(v.x); P1_PROC(v.y); P1_PROC(v.z); P1_PROC(v.w);
    }
    // tail: elements [n4a*4, n), block 0 warp 0 (< 160 elements)
    if (blockIdx.x == 0 && warp == 0) {
        const unsigned* xs = (const unsigned*)x4;
        for (int i = (n4a << 2) + lane; i < n; i += 32) {
            __syncwarp();
            if (*cnt >= WBUF - 32u) warp_flush(buf, cnt, lane);
            unsigned r = xs[i];
            P1_PROC(r);
        }
    }
#undef P1_PROC
    __syncwarp();
    warp_flush(buf, cnt, lane);   // final drain

    for (int o = 16; o; o >>= 1) zc += __shfl_down_sync(0xffffffffu, zc, o);
    if (lane == 0 && zc) atomicAdd(&g_zeros, (unsigned long long)zc);
    __syncthreads();
    for (int b = tid; b < 1024; b += THREADS) {
        unsigned s = shist[b];
        if (s) atomicAdd(&g_hist1[b], s);
    }
}

// ---------------- Scan 1: idx + coarse bin + rank
__global__ void scan1(long long n) {
    int t = threadIdx.x;
    unsigned c = g_hist1[t];
    unsigned candTot;
    unsigned incl = block_scan_1024(c, t, &candTot);

    long long zeros = (long long)g_zeros;
    long long below = n - (long long)candTot;   // elements with |x| < 2.0 (incl zeros)
    long long nnz = n - zeros;
    long long idx = (long long)floorf(0.997f * (float)nnz) + (n - nnz);
    if (idx > n - 1) idx = n - 1;
    if (idx < 0) idx = 0;
    int need = (below > idx) ? 1 : 0;
    if (t == 0) { g_need = need; g_idx = idx; }
    if (need) return;

    long long r = idx - below;
    long long inclL = (long long)incl;
    long long exclL = inclL - (long long)c;
    if (r >= exclL && r < inclL) {
        g_bin20 = 1024 + t;
        g_rank = r - exclL;
    }
}

// ---------------- Fallback (single block, exact, only if th < 2.0)
__global__ void fbk(const uint4* __restrict__ x4, int n4, int n) {
    if (!g_need) return;
    __shared__ unsigned sh[2048];
    __shared__ int sbin, sch;
    __shared__ long long srank, sr3;
    int t = threadIdx.x;                 // 1024 threads
    sh[t] = 0u; sh[t + 1024] = 0u;
    __syncthreads();
    int rem = n - (n4 << 2);
    for (int i = t; i < n4; i += 1024) {
        uint4 v = x4[i];
        atomicAdd(&sh[(v.x & 0x7fffffffu) >> 20], 1u);
        atomicAdd(&sh[(v.y & 0x7fffffffu) >> 20], 1u);
        atomicAdd(&sh[(v.z & 0x7fffffffu) >> 20], 1u);
        atomicAdd(&sh[(v.w & 0x7fffffffu) >> 20], 1u);
    }
    if (t < rem) atomicAdd(&sh[(((const unsigned*)x4)[(n4 << 2) + t] & 0x7fffffffu) >> 20], 1u);
    __syncthreads();
    unsigned tot;
    unsigned c0 = sh[2 * t], c1 = sh[2 * t + 1];
    unsigned incl = block_scan_1024(c0 + c1, t, &tot);
    long long r = g_idx;
    long long inclL = (long long)incl, exclL = inclL - (long long)(c0 + c1);
    if (r >= exclL && r < inclL) {
        if (r < exclL + (long long)c0) { sbin = 2 * t;     srank = r - exclL; }
        else                           { sbin = 2 * t + 1; srank = r - exclL - (long long)c0; }
    }
    __syncthreads();
    unsigned cb = (unsigned)sbin;
    long long r2 = srank;
    for (unsigned i = t; i < (1u << 20); i += 1024u) g_fb[i] = 0u;
    __syncthreads();
    for (int i = t; i < n4; i += 1024) {
        uint4 v = x4[i];
#define FB(r_) do { unsigned u = (r_) & 0x7fffffffu; \
        if ((u >> 20) == cb) atomicAdd(&g_fb[u & 0xFFFFFu], 1u); } while (0)
        FB(v.x); FB(v.y); FB(v.z); FB(v.w);
    }
    if (t < rem) { FB(((const unsigned*)x4)[(n4 << 2) + t]); }
#undef FB
    __syncthreads();
    unsigned s = 0u;
    for (int j = 0; j < 1024; j++) s += g_fb[t * 1024 + j];
    unsigned incl3 = block_scan_1024(s, t, &tot);
    long long incl3L = (long long)incl3, excl3L = incl3L - (long long)s;
    if (r2 >= excl3L && r2 < incl3L) { sch = t; sr3 = r2 - excl3L; }
    __syncthreads();
    int ch = sch;
    long long r3 = sr3;
    unsigned c4 = g_fb[(unsigned)ch * 1024u + (unsigned)t];
    unsigned incl4 = block_scan_1024(c4, t, &tot);
    long long incl4L = (long long)incl4, excl4L = incl4L - (long long)c4;
    if (r3 >= excl4L && r3 < incl4L) {
        unsigned bits = (cb << 20) | ((unsigned)ch * 1024u + (unsigned)t);
        float th = __uint_as_float(bits);
        g_th = th;
        g_step = th / 7.0f;
    }
}

// ---------------- Pass 2 (mid): bits [19:9] hist of target coarse bin, from buffer
__global__ void __launch_bounds__(THREADS) pass2mid(const uint4* __restrict__ x4,
                                                    int n4, int n) {
    if (g_need) return;
    __shared__ unsigned smid[2048];
    int tid = threadIdx.x;
    for (int i = tid; i < 2048; i += THREADS) smid[i] = 0u;
    __syncthreads();
    unsigned B = (unsigned)g_bin20;
    unsigned stride = gridDim.x * blockDim.x;
    unsigned t0 = blockIdx.x * blockDim.x + tid;
    if (!g_ovf) {
        unsigned tot = g_cur;
        for (unsigned i = t0; i < tot; i += stride) {
            unsigned u = g_cand[i];
            if ((u >> 20) == B) atomicAdd(&smid[(u >> 9) & 0x7FFu], 1u);
        }
    } else {
        for (int i = (int)t0; i < n4; i += (int)stride) {
            uint4 v = x4[i];
#define PM(r_) do { unsigned u = (r_) & 0x7fffffffu; \
        if ((u >> 20) == B) atomicAdd(&smid[(u >> 9) & 0x7FFu], 1u); } while (0)
            PM(v.x); PM(v.y); PM(v.z); PM(v.w);
        }
        int rem = n - (n4 << 2);
        if ((int)t0 < rem) { PM(((const unsigned*)x4)[(n4 << 2) + (int)t0]); }
#undef PM
    }
    __syncthreads();
    for (int b = tid; b < 2048; b += THREADS) {
        unsigned s = smid[b];
        if (s) atomicAdd(&g_mid[b], s);
    }
}

// ---------------- Scan M: locate mid bin -> g_top21, g_rank2
__global__ void scanM() {
    if (g_need) return;
    int t = threadIdx.x;
    unsigned tot;
    unsigned c0 = g_mid[2 * t], c1 = g_mid[2 * t + 1];
    unsigned incl = block_scan_1024(c0 + c1, t, &tot);
    long long r = g_rank;
    long long inclL = (long long)incl, exclL = inclL - (long long)(c0 + c1);
    if (r >= exclL && r < inclL) {
        unsigned m = (r < exclL + (long long)c0) ? (2u * (unsigned)t) : (2u * (unsigned)t + 1u);
        g_top21 = ((unsigned)g_bin20 << 11) | m;
        g_rank2 = (m & 1u) ? (r - exclL - (long long)c0) : (r - exclL);
    }
}

// ---------------- Pass 2 (low): bits [8:0] hist of target mid bin (tiny counts)
__global__ void __launch_bounds__(THREADS) pass2low(const uint4* __restrict__ x4,
                                                    int n4, int n) {
    if (g_need) return;
    unsigned T21 = g_top21;
    unsigned stride = gridDim.x * blockDim.x;
    unsigned t0 = blockIdx.x * blockDim.x + threadIdx.x;
    if (!g_ovf) {
        unsigned tot = g_cur;
        for (unsigned i = t0; i < tot; i += stride) {
            unsigned u = g_cand[i];
            if ((u >> 9) == T21) atomicAdd(&g_low[u & 0x1FFu], 1u);
        }
    } else {
        for (int i = (int)t0; i < n4; i += (int)stride) {
            uint4 v = x4[i];
#define PL(r_) do { unsigned u = (r_) & 0x7fffffffu; \
        if ((u >> 9) == T21) atomicAdd(&g_low[u & 0x1FFu], 1u); } while (0)
            PL(v.x); PL(v.y); PL(v.z); PL(v.w);
        }
        int rem = n - (n4 << 2);
        if ((int)t0 < rem) { PL(((const unsigned*)x4)[(n4 << 2) + (int)t0]); }
#undef PL
    }
}

// ---------------- Scan L: final 9 bits -> th, step
__global__ void scanL() {
    if (g_need) return;
    int t = threadIdx.x;                 // 1024 threads, bins only for t < 512
    unsigned tot;
    unsigned c = (t < 512) ? g_low[t] : 0u;
    unsigned incl = block_scan_1024(c, t, &tot);
    long long r = g_rank2;
    long long inclL = (long long)incl, exclL = inclL - (long long)c;
    if (t < 512 && r >= exclL && r < inclL) {
        unsigned bits = (g_top21 << 9) | (unsigned)t;
        float th = __uint_as_float(bits);
        g_th = th;
        g_step = th / 7.0f;   // n_lv_pos = 2^(4-1)-1 = 7
    }
}

// ---------------- Pass 3: quantize + tiny state reset for next replay
__device__ __forceinline__ float quant1(float v, float th, float step) {
    if (fabsf(v) <= th) return rintf(v / step) * step;  // IEEE div + RN-even (matches XLA)
    return v;
}

__global__ void __launch_bounds__(THREADS, 8) pass3(const float4* __restrict__ x4,
                                                    float4* __restrict__ o4,
                                                    int n4, int n) {
    int tid = threadIdx.x;
    float th = g_th;
    float step = g_step;
    int stride = GRID * THREADS;
    int i0 = blockIdx.x * THREADS + tid;
    if (th > 0.0f) {
        for (int i = i0; i < n4; i += stride) {
            float4 v = __ldcs(&x4[i]);
            v.x = quant1(v.x, th, step);
            v.y = quant1(v.y, th, step);
            v.z = quant1(v.z, th, step);
            v.w = quant1(v.w, th, step);
            __stcs(&o4[i], v);
        }
        int rem = n - (n4 << 2);
        if (blockIdx.x == 0 && tid < rem) {
            int i = (n4 << 2) + tid;
            ((float*)o4)[i] = quant1(((const float*)x4)[i], th, step);
        }
    } else {
        for (int i = i0; i < n4; i += stride) __stcs(&o4[i], __ldcs(&x4[i]));
        int rem = n - (n4 << 2);
        if (blockIdx.x == 0 && tid < rem) {
            int i = (n4 << 2) + tid;
            ((float*)o4)[i] = ((const float*)x4)[i];
        }
    }
    // ---- reset tiny device state for next graph replay
    if (blockIdx.x == 0) {
        for (int b = tid; b < 1024; b += THREADS) g_hist1[b] = 0u;
        for (int b = tid; b < 2048; b += THREADS) g_mid[b] = 0u;
        for (int b = tid; b < 512; b += THREADS) g_low[b] = 0u;
        if (tid == 0) { g_zeros = 0ull; g_cur = 0u; g_need = 0; g_ovf = 0; }
    }
}

extern "C" void kernel_launch(void* const* d_in, const int* in_sizes, int n_in,
                              void* d_out, int out_size) {
    const float* x = (const float*)d_in[0];
    int n = in_sizes[0];
    int n4 = n >> 2;
    int n4a = n4 & ~31;   // warp-aligned uint4 count

    pass1<<<GRID, THREADS>>>((const uint4*)x, n4a, n);
    scan1<<<1, 1024>>>((long long)n);
    fbk<<<1, 1024>>>((const uint4*)x, n4, n);             // gated (g_need)
    pass2mid<<<592, THREADS>>>((const uint4*)x, n4, n);   // ~12 MB buffer scan
    scanM<<<1, 1024>>>();
    pass2low<<<592, THREADS>>>((const uint4*)x, n4, n);   // ~12 MB buffer scan
    scanL<<<1, 1024>>>();
    pass3<<<GRID, THREADS>>>((const float4*)x, (float4*)d_out, n4, n);
}